// round 4
// baseline (speedup 1.0000x reference)
#include <cuda_runtime.h>

// AdaptiveMemory: out[row] = coefM * mem[vids[row]] + coefH * h_last[row]
//   alpha = sigmoid(dot(h_last[row], W_alpha) + b_alpha)
//   coefM = d + (1-d)*alpha ; coefH = (1-d)*(1-alpha)
// B = 4096 rows, D = 1024. Warp per row; no smem, no block barriers.
// Register diet: only hv[8] persists across the shfl reduction; mem chunks are
// loaded in the epilogue and consumed immediately. Target: 4 CTAs/SM.

#define D_DIM   1024
#define CHUNKS  8            // (D/4) / 32 lanes
#define THREADS 256          // 8 warps = 8 rows per block

__global__ __launch_bounds__(THREADS, 4)
void adaptive_memory_kernel(const float* __restrict__ h_last,
                            const int* __restrict__ vids,
                            const float* __restrict__ mem,
                            const float* __restrict__ W_alpha,
                            const float* __restrict__ b_alpha,
                            const float* __restrict__ medium_decay,
                            float* __restrict__ out,
                            int n_mem_rows) {
    const int warp = threadIdx.x >> 5;
    const int lane = threadIdx.x & 31;
    const int row  = blockIdx.x * (THREADS / 32) + warp;

    const float4* h4 = reinterpret_cast<const float4*>(h_last + (size_t)row * D_DIM);
    const float4* w4 = reinterpret_cast<const float4*>(W_alpha);

    int vid = vids[row];
    if (vid < 0) vid = 0;
    if (vid >= n_mem_rows) vid = n_mem_rows - 1;
    const float4* m4 = reinterpret_cast<const float4*>(mem + (size_t)vid * D_DIM);

    // h chunks persist (needed for both dot and blend): 32 regs.
    float4 hv[CHUNKS];
    #pragma unroll
    for (int j = 0; j < CHUNKS; j++) hv[j] = h4[lane + 32 * j];

    // Dot with W (L1/L2 resident). wv is transient.
    float p = 0.0f;
    #pragma unroll
    for (int j = 0; j < CHUNKS; j++) {
        float4 wv = w4[lane + 32 * j];
        p += hv[j].x * wv.x + hv[j].y * wv.y + hv[j].z * wv.z + hv[j].w * wv.w;
    }

    // Butterfly reduce: every lane ends with the full sum.
    #pragma unroll
    for (int off = 16; off > 0; off >>= 1)
        p += __shfl_xor_sync(0xFFFFFFFFu, p, off);

    const float sum   = p + b_alpha[0];
    const float alpha = 1.0f / (1.0f + __expf(-sum));
    const float d     = medium_decay[0];
    const float cM    = d + (1.0f - d) * alpha;
    const float cH    = (1.0f - d) * (1.0f - alpha);

    // Epilogue: mem chunks loaded here, consumed immediately (no long-lived
    // registers). Compiler front-batches these 8 loads within the unroll.
    float4* o4 = reinterpret_cast<float4*>(out + (size_t)row * D_DIM);
    #pragma unroll
    for (int j = 0; j < CHUNKS; j++) {
        float4 mv = m4[lane + 32 * j];
        float4 o;
        o.x = cM * mv.x + cH * hv[j].x;
        o.y = cM * mv.y + cH * hv[j].y;
        o.z = cM * mv.z + cH * hv[j].z;
        o.w = cM * mv.w + cH * hv[j].w;
        o4[lane + 32 * j] = o;
    }
}

extern "C" void kernel_launch(void* const* d_in, const int* in_sizes, int n_in,
                              void* d_out, int out_size) {
    const float* h_last       = (const float*)d_in[0];
    const int*   vids         = (const int*)d_in[1];
    const float* mem          = (const float*)d_in[2];
    const float* W_alpha      = (const float*)d_in[3];
    const float* b_alpha      = (const float*)d_in[4];
    const float* medium_decay = (const float*)d_in[5];
    float*       out          = (float*)d_out;

    const int B          = in_sizes[0] / D_DIM;  // 4096
    const int n_mem_rows = in_sizes[2] / D_DIM;  // 100000

    const int rows_per_block = THREADS / 32;
    adaptive_memory_kernel<<<B / rows_per_block, THREADS>>>(
        h_last, vids, mem, W_alpha, b_alpha, medium_decay, out, n_mem_rows);
}

// round 5
// speedup vs baseline: 1.0407x; 1.0407x over previous
#include <cuda_runtime.h>

// AdaptiveMemory: out[row] = coefM * mem[vids[row]] + coefH * h_last[row]
//   alpha = sigmoid(dot(h_last[row], W_alpha) + b_alpha)
//   coefM = d + (1-d)*alpha ; coefH = (1-d)*(1-alpha)
// B = 4096 rows, D = 1024. Warp per row; no smem, no barriers.
// 128-thread CTAs (4 rows) -> grid 1024: CTA-per-SM spread is 7 vs 6.92
// (1.2% tail) instead of 4 vs 3.46 (16% tail) with 256-thread CTAs.

#define D_DIM   1024
#define CHUNKS  8            // (D/4) / 32 lanes
#define THREADS 128          // 4 warps = 4 rows per block

__global__ __launch_bounds__(THREADS, 8)
void adaptive_memory_kernel(const float* __restrict__ h_last,
                            const int* __restrict__ vids,
                            const float* __restrict__ mem,
                            const float* __restrict__ W_alpha,
                            const float* __restrict__ b_alpha,
                            const float* __restrict__ medium_decay,
                            float* __restrict__ out,
                            int n_mem_rows) {
    const int warp = threadIdx.x >> 5;
    const int lane = threadIdx.x & 31;
    const int row  = blockIdx.x * (THREADS / 32) + warp;

    const float4* h4 = reinterpret_cast<const float4*>(h_last + (size_t)row * D_DIM);
    const float4* w4 = reinterpret_cast<const float4*>(W_alpha);

    int vid = vids[row];
    if (vid < 0) vid = 0;
    if (vid >= n_mem_rows) vid = n_mem_rows - 1;
    const float4* m4 = reinterpret_cast<const float4*>(mem + (size_t)vid * D_DIM);

    // h chunks persist (needed for both dot and blend): 32 regs.
    float4 hv[CHUNKS];
    #pragma unroll
    for (int j = 0; j < CHUNKS; j++) hv[j] = h4[lane + 32 * j];

    // Dot with W (L1/L2 resident). wv is transient.
    float p = 0.0f;
    #pragma unroll
    for (int j = 0; j < CHUNKS; j++) {
        float4 wv = w4[lane + 32 * j];
        p += hv[j].x * wv.x + hv[j].y * wv.y + hv[j].z * wv.z + hv[j].w * wv.w;
    }

    // Butterfly reduce: every lane ends with the full sum.
    #pragma unroll
    for (int off = 16; off > 0; off >>= 1)
        p += __shfl_xor_sync(0xFFFFFFFFu, p, off);

    const float sum   = p + b_alpha[0];
    const float alpha = 1.0f / (1.0f + __expf(-sum));
    const float d     = medium_decay[0];
    const float cM    = d + (1.0f - d) * alpha;
    const float cH    = (1.0f - d) * (1.0f - alpha);

    // Epilogue: mem chunks loaded here, consumed immediately.
    float4* o4 = reinterpret_cast<float4*>(out + (size_t)row * D_DIM);
    #pragma unroll
    for (int j = 0; j < CHUNKS; j++) {
        float4 mv = m4[lane + 32 * j];
        float4 o;
        o.x = cM * mv.x + cH * hv[j].x;
        o.y = cM * mv.y + cH * hv[j].y;
        o.z = cM * mv.z + cH * hv[j].z;
        o.w = cM * mv.w + cH * hv[j].w;
        o4[lane + 32 * j] = o;
    }
}

extern "C" void kernel_launch(void* const* d_in, const int* in_sizes, int n_in,
                              void* d_out, int out_size) {
    const float* h_last       = (const float*)d_in[0];
    const int*   vids         = (const int*)d_in[1];
    const float* mem          = (const float*)d_in[2];
    const float* W_alpha      = (const float*)d_in[3];
    const float* b_alpha      = (const float*)d_in[4];
    const float* medium_decay = (const float*)d_in[5];
    float*       out          = (float*)d_out;

    const int B          = in_sizes[0] / D_DIM;  // 4096
    const int n_mem_rows = in_sizes[2] / D_DIM;  // 100000

    const int rows_per_block = THREADS / 32;
    adaptive_memory_kernel<<<B / rows_per_block, THREADS>>>(
        h_last, vids, mem, W_alpha, b_alpha, medium_decay, out, n_mem_rows);
}